// round 11
// baseline (speedup 1.0000x reference)
#include <cuda_runtime.h>
#include <math.h>

#define PI_F 3.14159265358979323846f

// One block per batch image (128 blocks x 512 threads).
// final_state = C * m: m = REAL 16-vector of cos/sin(pi x) products (Rx phases
// folded into C), C = 16x16 complex circuit matrix (data-independent).
// Phase A: threads 0..255 build C cooperatively (thread (j=t>>4, i=t&15), gate
// partners via shfl within the 16-lane group).
// Phase B: 2 threads per patch (e = t&1): thread e computes rows 8e..8e+7 of
// C*m, partial <Z_q> sums, one shfl.bfly(1) reduce, e==0 writes 4 features.
// FC1 8-way split per output + shfl reduce, FC2.
__global__ __launch_bounds__(512, 1) void qnet_kernel(
    const float* __restrict__ x,      // [128,1,28,28]
    const float* __restrict__ weight, // [60]
    const float* __restrict__ fc1_w,  // [64,784]
    const float* __restrict__ fc1_b,  // [64]
    const float* __restrict__ fc2_w,  // [10,64]
    const float* __restrict__ fc2_b,  // [10]
    float* __restrict__ out)          // [128,10]
{
    __shared__ float4 ssu2[20];       // (ar, ai, br, bi) per (layer*4 + qubit)
    __shared__ float2 C2[16][16];     // C2[i][j]
    __shared__ float sfeat[784];
    __shared__ float sh[64];

    const int t = threadIdx.x;
    const int b = blockIdx.x;

    // U = Ry(c)*Rz(bb)*Ry(a) = [[alpha, -conj(beta)],[beta, conj(alpha)]]
    if (t < 20) {
        const int layer = t >> 2, q = t & 3;
        const int base = layer * 12;
        float sa, ca, sb, cb, sc, cc;
        __sincosf(0.5f * weight[base + q],     &sa, &ca);
        __sincosf(0.5f * weight[base + 4 + q], &sb, &cb);
        __sincosf(0.5f * weight[base + 8 + q], &sc, &cc);
        ssu2[t] = make_float4( cb * (cc * ca - sc * sa),
                              -sb * (cc * ca + sc * sa),
                               cb * (sc * ca + cc * sa),
                               sb * (cc * sa - sc * ca));
    }

    // Issue patch x loads early (both threads of a pair load the same 4 floats
    // -> L1 broadcast); consumed after phase A so DRAM latency hides under it.
    float px0, px1, px2, px3;
    const int patch = t >> 1;
    const int e = t & 1;
    if (t < 392) {
        const int pi_ = patch / 14, pj = patch % 14;
        const float* xb = x + b * 784 + (2 * pi_) * 28 + 2 * pj;
        px0 = xb[0]; px1 = xb[1]; px2 = xb[28]; px3 = xb[29];
    }
    __syncthreads();   // ssu2 ready

    // ---- Phase A: build C (threads 0..255, one amplitude each) ----
    if (t < 256) {
        const int j = t >> 4;         // column
        const int i = t & 15;         // amplitude index (q0=bit3 .. q3=bit0)

        // Init: amp i of folded column j (layer-0 U columns, (-i)^{j_q} folded).
        float arv = 1.f, aiv = 0.f;
        #pragma unroll
        for (int q = 0; q < 4; q++) {
            const float4 u = ssu2[q];
            const int jb = (j >> (3 - q)) & 1, ib = (i >> (3 - q)) & 1;
            float wr, wi;
            if (!jb) { wr = ib ?  u.z : u.x;  wi = ib ?  u.w : u.y; }
            else     { wr = ib ? -u.y : u.w;  wi = ib ? -u.x : u.z; }
            const float nr = arv * wr - aiv * wi;
            aiv = arv * wi + aiv * wr;
            arv = nr;
        }

        #pragma unroll
        for (int layer = 1; layer < 5; layer++) {
            // CNOT ring 0->1->2->3->0: conditional partner take
            #pragma unroll
            for (int q = 0; q < 4; q++) {
                const int cb = 8 >> q, tb = 8 >> ((q + 1) & 3);
                const float pr  = __shfl_xor_sync(0xffffffffu, arv, tb);
                const float pi2 = __shfl_xor_sync(0xffffffffu, aiv, tb);
                if (i & cb) { arv = pr; aiv = pi2; }
            }
            // Merged SU(2) per qubit: branch-free signed update
            #pragma unroll
            for (int q = 0; q < 4; q++) {
                const float4 u = ssu2[layer * 4 + q];
                const int st = 8 >> q;
                const float pr  = __shfl_xor_sync(0xffffffffu, arv, st);
                const float pi2 = __shfl_xor_sync(0xffffffffu, aiv, st);
                const bool hi = (i & st) != 0;
                const float ys = hi ? u.y : -u.y;
                const float zs = hi ? u.z : -u.z;
                const float nr = u.x * arv + ys * aiv + zs * pr  - u.w * pi2;
                const float ni = u.x * aiv - ys * arv + zs * pi2 + u.w * pr;
                arv = nr; aiv = ni;
            }
        }
        C2[i][j] = make_float2(arv, aiv);
    }
    __syncthreads();   // C ready

    // ---- Phase B: per-patch m + half of C*m per thread + expectations ----
    if (t < 392) {
        // shfl mask: warps 0..11 full, warp 12 lanes 0..7 active (392=12*32+8)
        const unsigned wmask = ((t >> 5) < 12) ? 0xffffffffu : 0x000000ffu;

        float c0, s0, c1, s1, c2, s2, c3, s3;
        __sincosf(PI_F * px0, &s0, &c0);
        __sincosf(PI_F * px1, &s1, &c1);
        __sincosf(PI_F * px2, &s2, &c2);
        __sincosf(PI_F * px3, &s3, &c3);
        float m01[4], m23[4];
        m01[0] = c0 * c1; m01[1] = c0 * s1; m01[2] = s0 * c1; m01[3] = s0 * s1;
        m23[0] = c2 * c3; m23[1] = c2 * s3; m23[2] = s2 * c3; m23[3] = s2 * s3;
        float m[16];
        #pragma unroll
        for (int j = 0; j < 16; j++) m[j] = m01[j >> 2] * m23[j & 3];

        // Rows 8e .. 8e+7:  p_i = |sum_j C[i][j] m[j]|^2
        const int ibase = e << 3;
        float p[8];
        #pragma unroll
        for (int r = 0; r < 8; r++) {
            const float4* crow = (const float4*)&C2[ibase + r][0];
            float accr = 0.f, acci = 0.f;
            #pragma unroll
            for (int jj = 0; jj < 8; jj++) {
                const float4 cc = crow[jj];
                accr += cc.x * m[2 * jj] + cc.z * m[2 * jj + 1];
                acci += cc.y * m[2 * jj] + cc.w * m[2 * jj + 1];
            }
            p[r] = accr * accr + acci * acci;
        }

        // Partial expectations over own rows. Row index i = ibase + r:
        // q0 sign = (e ? -1 : +1) (bit3); q1,q2,q3 signs from r bits 2,1,0.
        float e1 = 0.f, e2 = 0.f, e3 = 0.f, e0 = 0.f;
        #pragma unroll
        for (int r = 0; r < 8; r++) {
            e0 += p[r];
            e1 += (r & 4) ? -p[r] : p[r];
            e2 += (r & 2) ? -p[r] : p[r];
            e3 += (r & 1) ? -p[r] : p[r];
        }
        if (e) e0 = -e0;

        e0 += __shfl_xor_sync(wmask, e0, 1);
        e1 += __shfl_xor_sync(wmask, e1, 1);
        e2 += __shfl_xor_sync(wmask, e2, 1);
        e3 += __shfl_xor_sync(wmask, e3, 1);
        if (e == 0) *(float4*)&sfeat[patch * 4] = make_float4(e0, e1, e2, e3);
    }
    __syncthreads();

    // FC1: 64 outputs, each computed by 8 threads over 98-float k-slices (float2).
    {
        const int o = t >> 3, part = t & 7;
        const float2* wrow = (const float2*)(fc1_w + o * 784 + part * 98);
        const float2* frow = (const float2*)(sfeat + part * 98);
        float sum = 0.f;
        #pragma unroll 7
        for (int k = 0; k < 49; k++) {
            const float2 w2 = wrow[k];
            const float2 f2 = frow[k];
            sum += w2.x * f2.x + w2.y * f2.y;
        }
        sum += __shfl_xor_sync(0xffffffffu, sum, 1);
        sum += __shfl_xor_sync(0xffffffffu, sum, 2);
        sum += __shfl_xor_sync(0xffffffffu, sum, 4);
        if (part == 0) sh[o] = fmaxf(sum + fc1_b[o], 0.f);
    }
    __syncthreads();

    // FC2: 10 outputs
    if (t < 10) {
        float sum = fc2_b[t];
        const float* w2 = fc2_w + t * 64;
        #pragma unroll
        for (int k = 0; k < 64; k++) sum += w2[k] * sh[k];
        out[b * 10 + t] = sum;
    }
}

extern "C" void kernel_launch(void* const* d_in, const int* in_sizes, int n_in,
                              void* d_out, int out_size) {
    const float* x      = (const float*)d_in[0];
    const float* weight = (const float*)d_in[1];
    const float* fc1_w  = (const float*)d_in[2];
    const float* fc1_b  = (const float*)d_in[3];
    const float* fc2_w  = (const float*)d_in[4];
    const float* fc2_b  = (const float*)d_in[5];
    float* out = (float*)d_out;

    const int B = in_sizes[0] / 784;  // 128
    qnet_kernel<<<B, 512>>>(x, weight, fc1_w, fc1_b, fc2_w, fc2_b, out);
}

// round 12
// speedup vs baseline: 1.1577x; 1.1577x over previous
#include <cuda_runtime.h>
#include <math.h>

#define PI_F 3.14159265358979323846f

__device__ float g_feat[128 * 784];   // patch features, [image][patch*4+q]

// ---------------- K1: circuit -> features ----------------
// grid 196 x 128 threads; thread = one patch (p = blk*128 + t).
// Each block rebuilds C (16x16 complex circuit matrix) cooperatively:
// thread (i = t&15, columns j = t>>4 and (t>>4)+8) — columns are independent,
// gate partners via shfl within the 16-lane group (proven R9 phase-A update).
// Then per-thread: m vector (real), C*m, |.|^2, <Z_q> -> g_feat.
__global__ __launch_bounds__(128, 2) void circuit_kernel(
    const float* __restrict__ x,      // [128,1,28,28]
    const float* __restrict__ weight) // [60]
{
    __shared__ float4 ssu2[20];
    __shared__ float2 C2[16][16];

    const int t = threadIdx.x;

    // U = Ry(c)*Rz(bb)*Ry(a) = [[alpha, -conj(beta)],[beta, conj(alpha)]]
    if (t < 20) {
        const int layer = t >> 2, q = t & 3;
        const int base = layer * 12;
        float sa, ca, sb, cb, sc, cc;
        __sincosf(0.5f * weight[base + q],     &sa, &ca);
        __sincosf(0.5f * weight[base + 4 + q], &sb, &cb);
        __sincosf(0.5f * weight[base + 8 + q], &sc, &cc);
        ssu2[t] = make_float4( cb * (cc * ca - sc * sa),
                              -sb * (cc * ca + sc * sa),
                               cb * (sc * ca + cc * sa),
                               sb * (cc * sa - sc * ca));
    }

    // Early x loads for this thread's patch (consumed in phase B).
    const int p = blockIdx.x * 128 + t;     // 0..25087
    const int img = p / 196;
    const int pp  = p - img * 196;
    const float* xb = x + img * 784 + (pp / 14) * 56 + (pp % 14) * 2;
    const float px0 = xb[0], px1 = xb[1], px2 = xb[28], px3 = xb[29];
    __syncthreads();   // ssu2 ready

    // ---- Phase A: build C (2 columns per thread) ----
    {
        const int i  = t & 15;        // amplitude index (q0=bit3 .. q3=bit0)
        const int jA = t >> 4;        // column 0..7
        const int jB = jA + 8;        // column 8..15

        float arv[2], aiv[2];
        #pragma unroll
        for (int h = 0; h < 2; h++) {
            const int j = h ? jB : jA;
            float rr = 1.f, ii = 0.f;
            #pragma unroll
            for (int q = 0; q < 4; q++) {
                const float4 u = ssu2[q];
                const int jb = (j >> (3 - q)) & 1, ib = (i >> (3 - q)) & 1;
                float wr, wi;
                if (!jb) { wr = ib ?  u.z : u.x;  wi = ib ?  u.w : u.y; }
                else     { wr = ib ? -u.y : u.w;  wi = ib ? -u.x : u.z; }
                const float nr = rr * wr - ii * wi;
                ii = rr * wi + ii * wr;
                rr = nr;
            }
            arv[h] = rr; aiv[h] = ii;
        }

        #pragma unroll
        for (int layer = 1; layer < 5; layer++) {
            // CNOT ring 0->1->2->3->0: conditional partner take
            #pragma unroll
            for (int q = 0; q < 4; q++) {
                const int cb = 8 >> q, tb = 8 >> ((q + 1) & 3);
                #pragma unroll
                for (int h = 0; h < 2; h++) {
                    const float pr  = __shfl_xor_sync(0xffffffffu, arv[h], tb);
                    const float pi2 = __shfl_xor_sync(0xffffffffu, aiv[h], tb);
                    if (i & cb) { arv[h] = pr; aiv[h] = pi2; }
                }
            }
            // Merged SU(2) per qubit: branch-free signed update
            #pragma unroll
            for (int q = 0; q < 4; q++) {
                const float4 u = ssu2[layer * 4 + q];
                const int st = 8 >> q;
                const bool hi = (i & st) != 0;
                const float ys = hi ? u.y : -u.y;
                const float zs = hi ? u.z : -u.z;
                #pragma unroll
                for (int h = 0; h < 2; h++) {
                    const float pr  = __shfl_xor_sync(0xffffffffu, arv[h], st);
                    const float pi2 = __shfl_xor_sync(0xffffffffu, aiv[h], st);
                    const float nr = u.x * arv[h] + ys * aiv[h] + zs * pr  - u.w * pi2;
                    const float ni = u.x * aiv[h] - ys * arv[h] + zs * pi2 + u.w * pr;
                    arv[h] = nr; aiv[h] = ni;
                }
            }
        }
        C2[i][jA] = make_float2(arv[0], aiv[0]);
        C2[i][jB] = make_float2(arv[1], aiv[1]);
    }
    __syncthreads();   // C ready

    // ---- Phase B: per-patch m + C*m + expectations ----
    {
        float c0, s0, c1, s1, c2, s2, c3, s3;
        __sincosf(PI_F * px0, &s0, &c0);
        __sincosf(PI_F * px1, &s1, &c1);
        __sincosf(PI_F * px2, &s2, &c2);
        __sincosf(PI_F * px3, &s3, &c3);
        float m01[4], m23[4];
        m01[0] = c0 * c1; m01[1] = c0 * s1; m01[2] = s0 * c1; m01[3] = s0 * s1;
        m23[0] = c2 * c3; m23[1] = c2 * s3; m23[2] = s2 * c3; m23[3] = s2 * s3;
        float m[16];
        #pragma unroll
        for (int j = 0; j < 16; j++) m[j] = m01[j >> 2] * m23[j & 3];

        float pr[16];
        #pragma unroll
        for (int i = 0; i < 16; i++) {
            const float4* crow = (const float4*)&C2[i][0];  // broadcast LDS.128
            float accr = 0.f, acci = 0.f;
            #pragma unroll
            for (int jj = 0; jj < 8; jj++) {
                const float4 cc = crow[jj];
                accr += cc.x * m[2 * jj] + cc.z * m[2 * jj + 1];
                acci += cc.y * m[2 * jj] + cc.w * m[2 * jj + 1];
            }
            pr[i] = accr * accr + acci * acci;
        }

        float e[4];
        #pragma unroll
        for (int q = 0; q < 4; q++) {
            const int st = 8 >> q;
            float acc = 0.f;
            #pragma unroll
            for (int i = 0; i < 16; i++) acc += (i & st) ? -pr[i] : pr[i];
            e[q] = acc;
        }
        *(float4*)&g_feat[img * 784 + pp * 4] = make_float4(e[0], e[1], e[2], e[3]);
    }
}

// ---------------- K2: FC head ----------------
// grid 128 x 256 threads; block = image. Load 784 feats to smem (coalesced),
// then proven FC1 (4-way k-split + shfl reduce, relu) and FC2.
__global__ __launch_bounds__(256, 1) void fc_kernel(
    const float* __restrict__ fc1_w,  // [64,784]
    const float* __restrict__ fc1_b,  // [64]
    const float* __restrict__ fc2_w,  // [10,64]
    const float* __restrict__ fc2_b,  // [10]
    float* __restrict__ out)          // [128,10]
{
    __shared__ float sfeat[784];
    __shared__ float sh[64];

    const int t = threadIdx.x;
    const int b = blockIdx.x;

    if (t < 196)
        ((float4*)sfeat)[t] = ((const float4*)(g_feat + b * 784))[t];
    __syncthreads();

    {
        const int o = t >> 2, part = t & 3;
        const float4* wrow = (const float4*)(fc1_w + o * 784 + part * 196);
        const float4* frow = (const float4*)(sfeat + part * 196);
        float sum = 0.f;
        #pragma unroll 7
        for (int k = 0; k < 49; k++) {
            float4 w4 = wrow[k];
            float4 f4 = frow[k];
            sum += w4.x * f4.x + w4.y * f4.y + w4.z * f4.z + w4.w * f4.w;
        }
        sum += __shfl_xor_sync(0xffffffffu, sum, 1);
        sum += __shfl_xor_sync(0xffffffffu, sum, 2);
        if (part == 0) sh[o] = fmaxf(sum + fc1_b[o], 0.f);
    }
    __syncthreads();

    if (t < 10) {
        float sum = fc2_b[t];
        const float* w2 = fc2_w + t * 64;
        #pragma unroll
        for (int k = 0; k < 64; k++) sum += w2[k] * sh[k];
        out[b * 10 + t] = sum;
    }
}

extern "C" void kernel_launch(void* const* d_in, const int* in_sizes, int n_in,
                              void* d_out, int out_size) {
    const float* x      = (const float*)d_in[0];
    const float* weight = (const float*)d_in[1];
    const float* fc1_w  = (const float*)d_in[2];
    const float* fc1_b  = (const float*)d_in[3];
    const float* fc2_w  = (const float*)d_in[4];
    const float* fc2_b  = (const float*)d_in[5];
    float* out = (float*)d_out;

    circuit_kernel<<<196, 128>>>(x, weight);
    fc_kernel<<<128, 256>>>(fc1_w, fc1_b, fc2_w, fc2_b, out);
}